// round 8
// baseline (speedup 1.0000x reference)
#include <cuda_runtime.h>
#include <cstdint>
#include <cstddef>

constexpr int B_  = 4;
constexpr int DE  = 128;
constexpr int DO  = 512;
constexpr int K_  = 12960;   // 8*30*54
constexpr int Q_  = 1620;    // 30*54

constexpr int QT   = 96;
constexpr int NQT  = 17;          // ceil(1620/96)
constexpr int QPAD = NQT * QT;    // 1632
constexpr int KT   = 128;
constexpr int NKT  = 102;         // ceil(12960/128)

constexpr int MEM_ELEMS = B_ * DO * Q_;
constexpr float SCALE = 0.088388347648318447f;  // 1/sqrt(128)

// scratch: static device globals (no runtime allocation)
__device__ float g_e[(size_t)B_ * K_ * Q_];
__device__ float g_part[(size_t)B_ * NKT * QPAD];
__device__ float g_inv[(size_t)B_ * QPAD];

__device__ __forceinline__ uint32_t f2tf(float x) {
    uint32_t u;
    asm("cvt.rna.tf32.f32 %0, %1;" : "=r"(u) : "f"(x));
    return u;
}

// D(16x8) += A(16x8 row) * B(8x8 col), tf32 in, fp32 accum
__device__ __forceinline__ void mma8(float* c, const uint32_t* a, const uint32_t* b) {
    asm volatile(
        "mma.sync.aligned.m16n8k8.row.col.f32.tf32.tf32.f32 "
        "{%0,%1,%2,%3}, {%4,%5,%6,%7}, {%8,%9}, {%0,%1,%2,%3};\n"
        : "+f"(c[0]), "+f"(c[1]), "+f"(c[2]), "+f"(c[3])
        : "r"(a[0]), "r"(a[1]), "r"(a[2]), "r"(a[3]),
          "r"(b[0]), "r"(b[1]));
}

// ===========================================================================
// K1: e = exp(S/sqrt(DE)); S = m_in^T q_in. Also column partial sums.
// Block tile M=128(k) x N=96(q); warps 4(m) x 2(n); warp tile 32x48.
// ===========================================================================
__global__ __launch_bounds__(256, 2)
void k1_scores(const float* __restrict__ m_in, const float* __restrict__ q_in)
{
    __shared__ uint32_t As[128 * 36];   // [kk][dd], stride 36 -> conflict-free frag loads
    __shared__ uint32_t Bs[96 * 36];    // [q][dd]
    __shared__ float    cs[4 * 96];

    const int tid  = threadIdx.x;
    const int wid  = tid >> 5;
    const int lane = tid & 31;
    const int g    = lane >> 2;
    const int tg   = lane & 3;
    const int wm   = wid & 3;
    const int wn   = wid >> 2;

    const int kt = blockIdx.x;
    const int qt = blockIdx.y;
    const int b  = blockIdx.z;
    const int k0 = kt * KT;
    const int q0 = qt * QT;

    const float* mi = m_in + (size_t)b * DE * K_;
    const float* qi = q_in + (size_t)b * DE * Q_;

    float acc[2][6][4];
#pragma unroll
    for (int mt = 0; mt < 2; ++mt)
#pragma unroll
        for (int nt = 0; nt < 6; ++nt)
#pragma unroll
            for (int j = 0; j < 4; ++j) acc[mt][nt][j] = 0.f;

    for (int dc = 0; dc < 4; ++dc) {     // 4 chunks of 32 over d
#pragma unroll
        for (int it = 0; it < 16; ++it) {                  // A: 128x32
            int i  = tid + it * 256;
            int kk = i & 127;
            int dd = i >> 7;
            int kg = k0 + kk;
            float v = (kg < K_) ? mi[(size_t)(dc * 32 + dd) * K_ + kg] : 0.f;
            As[kk * 36 + dd] = f2tf(v);
        }
#pragma unroll
        for (int it = 0; it < 12; ++it) {                  // B: 96x32
            int i  = tid + it * 256;
            int q  = i % 96;
            int dd = i / 96;
            int qg = q0 + q;
            float v = (qg < Q_) ? qi[(size_t)(dc * 32 + dd) * Q_ + qg] : 0.f;
            Bs[q * 36 + dd] = f2tf(v);
        }
        __syncthreads();

#pragma unroll
        for (int ks = 0; ks < 4; ++ks) {
            const int c = ks * 8 + tg;
            uint32_t af[2][4];
#pragma unroll
            for (int mt = 0; mt < 2; ++mt) {
                int r = wm * 32 + mt * 16 + g;
                af[mt][0] = As[r * 36 + c];
                af[mt][1] = As[(r + 8) * 36 + c];
                af[mt][2] = As[r * 36 + c + 4];
                af[mt][3] = As[(r + 8) * 36 + c + 4];
            }
#pragma unroll
            for (int nt = 0; nt < 6; ++nt) {
                int n = wn * 48 + nt * 8 + g;
                uint32_t bf[2] = { Bs[n * 36 + c], Bs[n * 36 + c + 4] };
                mma8(acc[0][nt], af[0], bf);
                mma8(acc[1][nt], af[1], bf);
            }
        }
        __syncthreads();
    }

    // exp + masked column sums
    float ls[6][2];
#pragma unroll
    for (int nt = 0; nt < 6; ++nt) { ls[nt][0] = 0.f; ls[nt][1] = 0.f; }

#pragma unroll
    for (int mt = 0; mt < 2; ++mt)
#pragma unroll
        for (int nt = 0; nt < 6; ++nt)
#pragma unroll
            for (int j = 0; j < 4; ++j) {
                int r  = wm * 32 + mt * 16 + ((j & 2) ? (g + 8) : g);
                int kg = k0 + r;
                float e = (kg < K_) ? __expf(acc[mt][nt][j] * SCALE) : 0.f;
                acc[mt][nt][j] = e;
                ls[nt][j & 1] += e;
            }

#pragma unroll
    for (int nt = 0; nt < 6; ++nt)
#pragma unroll
        for (int p = 0; p < 2; ++p) {
            float v = ls[nt][p];
            v += __shfl_xor_sync(0xffffffffu, v, 4);
            v += __shfl_xor_sync(0xffffffffu, v, 8);
            v += __shfl_xor_sync(0xffffffffu, v, 16);
            if (g == 0) cs[wm * 96 + wn * 48 + nt * 8 + tg * 2 + p] = v;
        }
    __syncthreads();

    if (tid < 96) {
        float s = cs[tid] + cs[96 + tid] + cs[192 + tid] + cs[288 + tid];
        g_part[((size_t)b * NKT + kt) * QPAD + qt * QT + tid] = s;
    }

    // stage e through smem for coalesced g_e stores
    float* stg = reinterpret_cast<float*>(As);   // 32 x (stride 100)
#pragma unroll 1
    for (int chunk = 0; chunk < 4; ++chunk) {
        __syncthreads();
        if (wm == chunk) {
#pragma unroll
            for (int mt = 0; mt < 2; ++mt)
#pragma unroll
                for (int nt = 0; nt < 6; ++nt)
#pragma unroll
                    for (int j = 0; j < 4; ++j) {
                        int r = mt * 16 + ((j & 2) ? (g + 8) : g);
                        int c = wn * 48 + nt * 8 + tg * 2 + (j & 1);
                        stg[r * 100 + c] = acc[mt][nt][j];
                    }
        }
        __syncthreads();
        for (int i = tid; i < 32 * 96; i += 256) {
            int r = i / 96, c = i - r * 96;
            int kg = k0 + chunk * 32 + r;
            int qg = q0 + c;
            if (kg < K_ && qg < Q_)
                g_e[((size_t)b * K_ + kg) * Q_ + qg] = stg[r * 100 + c];
        }
    }
}

// ===========================================================================
// K2: g_inv[b,q] = 1 / (exp(const) + sum_kt g_part)
// ===========================================================================
__global__ void k2_inv(const float* __restrict__ cst)
{
    int t = blockIdx.x * blockDim.x + threadIdx.x;
    if (t >= B_ * QPAD) return;
    int b  = t / QPAD;
    int qp = t - b * QPAD;
    float d = expf(cst[0]);
    const float* gp = g_part + (size_t)b * NKT * QPAD + qp;
    for (int kt = 0; kt < NKT; ++kt) d += gp[(size_t)kt * QPAD];
    g_inv[t] = 1.f / d;
}

// ===========================================================================
// K3: mem = m_out @ p, with p = g_e * inv formed on the B-load path.
// Blocks also stream normalized p to d_out, interleaved by (kc&3)==dot.
// Block tile M=128(d_o) x N=96(q); 405 k-chunks of 32 (exact).
// ===========================================================================
__global__ __launch_bounds__(256, 2)
void k3_out(const float* __restrict__ m_out,
            float* __restrict__ out_mem, float* __restrict__ out_p)
{
    __shared__ uint32_t As[128 * 36];    // [do][kc]
    __shared__ uint32_t Bs[96 * 36];     // [q][kc]
    __shared__ float    sinv[96];

    const int tid  = threadIdx.x;
    const int wid  = tid >> 5;
    const int lane = tid & 31;
    const int g    = lane >> 2;
    const int tg   = lane & 3;
    const int wm   = wid & 3;
    const int wn   = wid >> 2;

    const int dot = blockIdx.x;   // 0..3
    const int qt  = blockIdx.y;   // 0..16
    const int b   = blockIdx.z;
    const int q0  = qt * QT;
    const int do0 = dot * 128;

    if (tid < 96) sinv[tid] = g_inv[(size_t)b * QPAD + q0 + tid];

    const float* mo   = m_out + ((size_t)b * DO + do0) * K_;
    const float* ep   = g_e + (size_t)b * K_ * Q_;
    float*       pout = out_p + (size_t)b * K_ * Q_;

    float acc[2][6][4];
#pragma unroll
    for (int mt = 0; mt < 2; ++mt)
#pragma unroll
        for (int nt = 0; nt < 6; ++nt)
#pragma unroll
            for (int j = 0; j < 4; ++j) acc[mt][nt][j] = 0.f;

    __syncthreads();

#pragma unroll 1
    for (int kc = 0; kc < 405; ++kc) {     // 405*32 = 12960 exact
        const int k0 = kc * 32;
        const bool pw = ((kc & 3) == dot); // balanced p-write duty

        // A: m_out [128 do x 32 k] -- contiguous in k, conflict-free stores
#pragma unroll
        for (int it = 0; it < 16; ++it) {
            int i   = tid + it * 256;
            int kk  = i & 31;
            int row = i >> 5;
            As[row * 36 + kk] = f2tf(mo[(size_t)row * K_ + k0 + kk]);
        }
        // B: p tile [96 q x 32 k] from g_e (row k contiguous in q) * inv
#pragma unroll
        for (int it = 0; it < 12; ++it) {
            int i  = tid + it * 256;
            int q  = i % 96;
            int kk = i / 96;
            int qg = q0 + q;
            float bv = 0.f;
            if (qg < Q_) {
                bv = ep[(size_t)(k0 + kk) * Q_ + qg] * sinv[q];
                if (pw) pout[(size_t)(k0 + kk) * Q_ + qg] = bv;
            }
            Bs[q * 36 + kk] = f2tf(bv);
        }
        __syncthreads();

#pragma unroll
        for (int ks = 0; ks < 4; ++ks) {
            const int c = ks * 8 + tg;
            uint32_t af[2][4];
#pragma unroll
            for (int mt = 0; mt < 2; ++mt) {
                int r = wm * 32 + mt * 16 + g;
                af[mt][0] = As[r * 36 + c];
                af[mt][1] = As[(r + 8) * 36 + c];
                af[mt][2] = As[r * 36 + c + 4];
                af[mt][3] = As[(r + 8) * 36 + c + 4];
            }
#pragma unroll
            for (int nt = 0; nt < 6; ++nt) {
                int n = wn * 48 + nt * 8 + g;
                uint32_t bf[2] = { Bs[n * 36 + c], Bs[n * 36 + c + 4] };
                mma8(acc[0][nt], af[0], bf);
                mma8(acc[1][nt], af[1], bf);
            }
        }
        __syncthreads();
    }

    // epilogue: write mem
#pragma unroll
    for (int mt = 0; mt < 2; ++mt)
#pragma unroll
        for (int nt = 0; nt < 6; ++nt)
#pragma unroll
            for (int j = 0; j < 4; ++j) {
                int r  = wm * 32 + mt * 16 + ((j & 2) ? (g + 8) : g);
                int cq = wn * 48 + nt * 8 + tg * 2 + (j & 1);
                int qg = q0 + cq;
                if (qg < Q_)
                    out_mem[((size_t)b * DO + do0 + r) * Q_ + qg] = acc[mt][nt][j];
            }
}

extern "C" void kernel_launch(void* const* d_in, const int* in_sizes, int n_in,
                              void* d_out, int out_size) {
    const float* m_in  = (const float*)d_in[0];
    const float* m_out = (const float*)d_in[1];
    const float* q_in  = (const float*)d_in[2];
    const float* cst   = (const float*)d_in[3];
    float* out = (float*)d_out;

    k1_scores<<<dim3(NKT, NQT, B_), 256>>>(m_in, q_in);
    k2_inv<<<(B_ * QPAD + 255) / 256, 256>>>(cst);
    k3_out<<<dim3(4, NQT, B_), 256>>>(m_out, out, out + MEM_ELEMS);
}

// round 10
// speedup vs baseline: 3.0982x; 3.0982x over previous
#include <cuda_runtime.h>
#include <cstdint>
#include <cstddef>

constexpr int B_  = 4;
constexpr int DE  = 128;
constexpr int DO  = 512;
constexpr int K_  = 12960;   // 8*30*54
constexpr int Q_  = 1620;    // 30*54

constexpr int QT   = 96;
constexpr int NQT  = 17;          // ceil(1620/96)
constexpr int QPAD = NQT * QT;    // 1632
constexpr int KT   = 128;
constexpr int NKT  = 102;         // ceil(12960/128)

constexpr int MEM_ELEMS = B_ * DO * Q_;
constexpr float SCALE = 0.088388347648318447f;  // 1/sqrt(128)

// scratch: static device globals (no runtime allocation)
// g_e padded: K3's cp.async tail chunks may read up to 48B past the last row.
__device__ float g_e[(size_t)B_ * K_ * Q_ + 64];
__device__ float g_mo[(size_t)B_ * DO * K_];          // tf32-pre-rounded m_out
__device__ float g_part[(size_t)B_ * NKT * QPAD];
__device__ float g_inv[(size_t)B_ * QPAD];

__device__ __forceinline__ uint32_t f2tf(float x) {
    uint32_t u;
    asm("cvt.rna.tf32.f32 %0, %1;" : "=r"(u) : "f"(x));
    return u;
}

// D(16x8) += A(16x8 row) * B(8x8 col), tf32 in, fp32 accum
__device__ __forceinline__ void mma8(float* c, const uint32_t* a, const uint32_t* b) {
    asm volatile(
        "mma.sync.aligned.m16n8k8.row.col.f32.tf32.tf32.f32 "
        "{%0,%1,%2,%3}, {%4,%5,%6,%7}, {%8,%9}, {%0,%1,%2,%3};\n"
        : "+f"(c[0]), "+f"(c[1]), "+f"(c[2]), "+f"(c[3])
        : "r"(a[0]), "r"(a[1]), "r"(a[2]), "r"(a[3]),
          "r"(b[0]), "r"(b[1]));
}

__device__ __forceinline__ uint32_t s2u(const void* p) {
    return (uint32_t)__cvta_generic_to_shared(p);
}
__device__ __forceinline__ void cpa16(uint32_t dst, const float* src) {
    asm volatile("cp.async.cg.shared.global [%0], [%1], 16;\n" :: "r"(dst), "l"(src));
}
__device__ __forceinline__ void cpcommit() {
    asm volatile("cp.async.commit_group;\n");
}

// ===========================================================================
// K0: pre-round m_out to tf32 (so K3's cp.async path needs no conversion)
// ===========================================================================
__global__ void k0_round(const float* __restrict__ src)
{
    size_t i = ((size_t)blockIdx.x * 256 + threadIdx.x) * 4;
    float4 v = *reinterpret_cast<const float4*>(src + i);
    v.x = __uint_as_float(f2tf(v.x));
    v.y = __uint_as_float(f2tf(v.y));
    v.z = __uint_as_float(f2tf(v.z));
    v.w = __uint_as_float(f2tf(v.w));
    *reinterpret_cast<float4*>(g_mo + i) = v;
}

// ===========================================================================
// K1: e = exp(S/sqrt(DE)); S = m_in^T q_in. Column partial sums to g_part.
// g_e is stored tf32-ROUNDED so K3 can consume raw bits exactly.
// ===========================================================================
__global__ __launch_bounds__(256, 2)
void k1_scores(const float* __restrict__ m_in, const float* __restrict__ q_in)
{
    __shared__ uint32_t As[128 * 36];
    __shared__ uint32_t Bs[96 * 36];
    __shared__ float    cs[4 * 96];

    const int tid  = threadIdx.x;
    const int wid  = tid >> 5;
    const int lane = tid & 31;
    const int g    = lane >> 2;
    const int tg   = lane & 3;
    const int wm   = wid & 3;
    const int wn   = wid >> 2;

    const int kt = blockIdx.x;
    const int qt = blockIdx.y;
    const int b  = blockIdx.z;
    const int k0 = kt * KT;
    const int q0 = qt * QT;

    const float* mi = m_in + (size_t)b * DE * K_;
    const float* qi = q_in + (size_t)b * DE * Q_;

    float acc[2][6][4];
#pragma unroll
    for (int mt = 0; mt < 2; ++mt)
#pragma unroll
        for (int nt = 0; nt < 6; ++nt)
#pragma unroll
            for (int j = 0; j < 4; ++j) acc[mt][nt][j] = 0.f;

    for (int dc = 0; dc < 4; ++dc) {
#pragma unroll
        for (int it = 0; it < 16; ++it) {
            int i  = tid + it * 256;
            int kk = i & 127;
            int dd = i >> 7;
            int kg = k0 + kk;
            float v = (kg < K_) ? mi[(size_t)(dc * 32 + dd) * K_ + kg] : 0.f;
            As[kk * 36 + dd] = f2tf(v);
        }
#pragma unroll
        for (int it = 0; it < 12; ++it) {
            int i  = tid + it * 256;
            int q  = i % 96;
            int dd = i / 96;
            int qg = q0 + q;
            float v = (qg < Q_) ? qi[(size_t)(dc * 32 + dd) * Q_ + qg] : 0.f;
            Bs[q * 36 + dd] = f2tf(v);
        }
        __syncthreads();

#pragma unroll
        for (int ks = 0; ks < 4; ++ks) {
            const int c = ks * 8 + tg;
            uint32_t af[2][4];
#pragma unroll
            for (int mt = 0; mt < 2; ++mt) {
                int r = wm * 32 + mt * 16 + g;
                af[mt][0] = As[r * 36 + c];
                af[mt][1] = As[(r + 8) * 36 + c];
                af[mt][2] = As[r * 36 + c + 4];
                af[mt][3] = As[(r + 8) * 36 + c + 4];
            }
#pragma unroll
            for (int nt = 0; nt < 6; ++nt) {
                int n = wn * 48 + nt * 8 + g;
                uint32_t bf[2] = { Bs[n * 36 + c], Bs[n * 36 + c + 4] };
                mma8(acc[0][nt], af[0], bf);
                mma8(acc[1][nt], af[1], bf);
            }
        }
        __syncthreads();
    }

    float ls[6][2];
#pragma unroll
    for (int nt = 0; nt < 6; ++nt) { ls[nt][0] = 0.f; ls[nt][1] = 0.f; }

#pragma unroll
    for (int mt = 0; mt < 2; ++mt)
#pragma unroll
        for (int nt = 0; nt < 6; ++nt)
#pragma unroll
            for (int j = 0; j < 4; ++j) {
                int r  = wm * 32 + mt * 16 + ((j & 2) ? (g + 8) : g);
                int kg = k0 + r;
                float e = (kg < K_) ? __expf(acc[mt][nt][j] * SCALE) : 0.f;
                acc[mt][nt][j] = e;
                ls[nt][j & 1] += e;
            }

#pragma unroll
    for (int nt = 0; nt < 6; ++nt)
#pragma unroll
        for (int p = 0; p < 2; ++p) {
            float v = ls[nt][p];
            v += __shfl_xor_sync(0xffffffffu, v, 4);
            v += __shfl_xor_sync(0xffffffffu, v, 8);
            v += __shfl_xor_sync(0xffffffffu, v, 16);
            if (g == 0) cs[wm * 96 + wn * 48 + nt * 8 + tg * 2 + p] = v;
        }
    __syncthreads();

    if (tid < 96) {
        float s = cs[tid] + cs[96 + tid] + cs[192 + tid] + cs[288 + tid];
        g_part[((size_t)b * NKT + kt) * QPAD + qt * QT + tid] = s;
    }

    float* stg = reinterpret_cast<float*>(As);
#pragma unroll 1
    for (int chunk = 0; chunk < 4; ++chunk) {
        __syncthreads();
        if (wm == chunk) {
#pragma unroll
            for (int mt = 0; mt < 2; ++mt)
#pragma unroll
                for (int nt = 0; nt < 6; ++nt)
#pragma unroll
                    for (int j = 0; j < 4; ++j) {
                        int r = mt * 16 + ((j & 2) ? (g + 8) : g);
                        int c = wn * 48 + nt * 8 + tg * 2 + (j & 1);
                        // store TF32-ROUNDED e
                        stg[r * 100 + c] = __uint_as_float(f2tf(acc[mt][nt][j]));
                    }
        }
        __syncthreads();
        for (int i = tid; i < 32 * 96; i += 256) {
            int r = i / 96, c = i - r * 96;
            int kg = k0 + chunk * 32 + r;
            int qg = q0 + c;
            if (kg < K_ && qg < Q_)
                g_e[((size_t)b * K_ + kg) * Q_ + qg] = stg[r * 100 + c];
        }
    }
}

// ===========================================================================
// K2: g_inv[b,q] = 1 / (exp(const) + sum_kt g_part)
// ===========================================================================
__global__ void k2_inv(const float* __restrict__ cst)
{
    int t = blockIdx.x * blockDim.x + threadIdx.x;
    if (t >= B_ * QPAD) return;
    int b  = t / QPAD;
    int qp = t - b * QPAD;
    float d = expf(cst[0]);
    const float* gp = g_part + (size_t)b * NKT * QPAD + qp;
#pragma unroll 4
    for (int kt = 0; kt < NKT; ++kt) d += gp[(size_t)kt * QPAD];
    g_inv[t] = 1.f / d;
}

// ===========================================================================
// K3: U = g_mo @ g_e via cp.async double-buffered pipeline (no cvt in loop),
//     mem = U * inv[q] in epilogue; p = g_e*inv written from smem B tile
//     on a 1/4 duty cycle per dot-block.
// Block tile M=128(d_o) x N=96(q); 405 k-chunks of 32 (exact).
// ===========================================================================
constexpr int ASTR  = 128 * 36;   // floats per A buffer (stride 36: conflict-free)
constexpr int BSTR  = 32 * 104;   // floats per B buffer (stride 104: conflict-free)
constexpr int SMEMF = 2 * ASTR + 2 * BSTR + 96;   // 15968 floats = 63872 B

__global__ __launch_bounds__(256, 2)
void k3_out(float* __restrict__ out_mem, float* __restrict__ out_p)
{
    extern __shared__ float sm[];
    float* Ab   = sm;
    float* Bb   = sm + 2 * ASTR;
    float* sinv = sm + 2 * ASTR + 2 * BSTR;

    const int tid  = threadIdx.x;
    const int wid  = tid >> 5;
    const int lane = tid & 31;
    const int g    = lane >> 2;
    const int tg   = lane & 3;
    const int wm   = wid & 3;
    const int wn   = wid >> 2;

    const int dot = blockIdx.x;   // 0..3
    const int qt  = blockIdx.y;   // 0..16
    const int b   = blockIdx.z;
    const int q0  = qt * QT;
    const int do0 = dot * 128;

    if (tid < 96) sinv[tid] = g_inv[(size_t)b * QPAD + q0 + tid];

    // per-thread cp.async descriptors (fixed across kc; pointers advance)
    const float* asrc[4]; uint32_t aoff[4];
#pragma unroll
    for (int it = 0; it < 4; ++it) {
        int i = tid + it * 256;          // A tile: 128 rows x 32 floats = 1024 chunks
        int row = i >> 3;
        int kc4 = (i & 7) * 4;
        asrc[it] = g_mo + ((size_t)b * DO + do0 + row) * K_ + kc4;
        aoff[it] = (uint32_t)((row * 36 + kc4) * 4);
    }
    const float* bsrc[3]; uint32_t boff[3]; int bkk[3], bqc[3];
#pragma unroll
    for (int it = 0; it < 3; ++it) {
        int i = tid + it * 256;          // B tile: 32 rows x 96 floats = 768 chunks
        int kk = i / 24;
        int qc = (i - kk * 24) * 4;
        bkk[it] = kk; bqc[it] = qc;
        bsrc[it] = g_e + (size_t)b * K_ * Q_ + (size_t)kk * Q_ + q0 + qc;
        boff[it] = (uint32_t)((kk * 104 + qc) * 4);
    }
    const uint32_t Abase = s2u(Ab);
    const uint32_t Bbase = s2u(Bb);

    float acc[2][6][4];
#pragma unroll
    for (int mt = 0; mt < 2; ++mt)
#pragma unroll
        for (int nt = 0; nt < 6; ++nt)
#pragma unroll
            for (int j = 0; j < 4; ++j) acc[mt][nt][j] = 0.f;

    // prologue: stage kc=0 into buffer 0
#pragma unroll
    for (int it = 0; it < 4; ++it) cpa16(Abase + aoff[it], asrc[it]);
#pragma unroll
    for (int it = 0; it < 3; ++it) cpa16(Bbase + boff[it], bsrc[it]);
    cpcommit();
#pragma unroll
    for (int it = 0; it < 4; ++it) asrc[it] += 32;
#pragma unroll
    for (int it = 0; it < 3; ++it) bsrc[it] += (size_t)32 * Q_;

    float* pout = out_p + (size_t)b * K_ * Q_;

#pragma unroll 1
    for (int kc = 0; kc < 405; ++kc) {
        if (kc < 404) {
            const uint32_t sa = Abase + ((kc + 1) & 1) * (ASTR * 4);
            const uint32_t sb = Bbase + ((kc + 1) & 1) * (BSTR * 4);
#pragma unroll
            for (int it = 0; it < 4; ++it) cpa16(sa + aoff[it], asrc[it]);
#pragma unroll
            for (int it = 0; it < 3; ++it) cpa16(sb + boff[it], bsrc[it]);
            cpcommit();
#pragma unroll
            for (int it = 0; it < 4; ++it) asrc[it] += 32;
#pragma unroll
            for (int it = 0; it < 3; ++it) bsrc[it] += (size_t)32 * Q_;
            asm volatile("cp.async.wait_group 1;\n" ::: "memory");
        } else {
            asm volatile("cp.async.wait_group 0;\n" ::: "memory");
        }
        __syncthreads();

        const float* A  = Ab + (kc & 1) * ASTR;
        const float* Bv = Bb + (kc & 1) * BSTR;

#pragma unroll
        for (int ks = 0; ks < 4; ++ks) {
            const int c = ks * 8 + tg;
            uint32_t af[2][4];
#pragma unroll
            for (int mt = 0; mt < 2; ++mt) {
                int r = wm * 32 + mt * 16 + g;
                af[mt][0] = __float_as_uint(A[r * 36 + c]);
                af[mt][1] = __float_as_uint(A[(r + 8) * 36 + c]);
                af[mt][2] = __float_as_uint(A[r * 36 + c + 4]);
                af[mt][3] = __float_as_uint(A[(r + 8) * 36 + c + 4]);
            }
#pragma unroll
            for (int nt = 0; nt < 6; ++nt) {
                int n = wn * 48 + nt * 8 + g;
                uint32_t bf[2] = { __float_as_uint(Bv[c * 104 + n]),
                                   __float_as_uint(Bv[(c + 4) * 104 + n]) };
                mma8(acc[0][nt], af[0], bf);
                mma8(acc[1][nt], af[1], bf);
            }
        }

        // p output: normalized e, written from the smem tile (1/4 duty cycle)
        if ((kc & 3) == dot) {
            const int k0 = kc * 32;
#pragma unroll
            for (int it = 0; it < 3; ++it) {
                const int kk = bkk[it], qc = bqc[it];
                float4 v = *reinterpret_cast<const float4*>(Bv + kk * 104 + qc);
                float4 w;
                w.x = v.x * sinv[qc];
                w.y = v.y * sinv[qc + 1];
                w.z = v.z * sinv[qc + 2];
                w.w = v.w * sinv[qc + 3];
                const int qg = q0 + qc;
                float* dst = pout + (size_t)(k0 + kk) * Q_ + qg;
                if (qg + 3 < Q_) {
                    *reinterpret_cast<float4*>(dst) = w;
                } else {
                    if (qg     < Q_) dst[0] = w.x;
                    if (qg + 1 < Q_) dst[1] = w.y;
                    if (qg + 2 < Q_) dst[2] = w.z;
                    if (qg + 3 < Q_) dst[3] = w.w;
                }
            }
        }
        __syncthreads();
    }

    // epilogue: mem = U * inv[q]
#pragma unroll
    for (int mt = 0; mt < 2; ++mt)
#pragma unroll
        for (int nt = 0; nt < 6; ++nt)
#pragma unroll
            for (int j = 0; j < 4; ++j) {
                int r  = wm * 32 + mt * 16 + ((j & 2) ? (g + 8) : g);
                int cq = wn * 48 + nt * 8 + tg * 2 + (j & 1);
                int qg = q0 + cq;
                if (qg < Q_)
                    out_mem[((size_t)b * DO + do0 + r) * Q_ + qg] =
                        acc[mt][nt][j] * sinv[cq];
            }
}

extern "C" void kernel_launch(void* const* d_in, const int* in_sizes, int n_in,
                              void* d_out, int out_size) {
    const float* m_in  = (const float*)d_in[0];
    const float* m_out = (const float*)d_in[1];
    const float* q_in  = (const float*)d_in[2];
    const float* cst   = (const float*)d_in[3];
    float* out = (float*)d_out;

    cudaFuncSetAttribute(k3_out, cudaFuncAttributeMaxDynamicSharedMemorySize,
                         SMEMF * 4);

    k0_round<<<(B_ * DO * K_) / (4 * 256), 256>>>(m_out);            // 25920 blocks, exact
    k1_scores<<<dim3(NKT, NQT, B_), 256>>>(m_in, q_in);
    k2_inv<<<(B_ * QPAD + 255) / 256, 256>>>(cst);
    k3_out<<<dim3(4, NQT, B_), 256, SMEMF * 4>>>(out, out + MEM_ELEMS);
}